// round 15
// baseline (speedup 1.0000x reference)
#include <cuda_runtime.h>
#include <cuda_fp16.h>
#include <cstdint>
#include <cstddef>

#define DI __device__ __forceinline__

// ---------------------------------------------------------------------------
// Problem constants
// ---------------------------------------------------------------------------
constexpr int B_ = 8;
constexpr int S_ = 2048;
constexpr int D_ = 1024;
constexpr int F_ = 4096;

// K per pipeline chunk = 128 (two 64-col subtiles per operand per stage).
// Double-buffered stages -> single __syncthreads per 128-K chunk.
constexpr int G1_STAGE = 96 * 1024;          // X(32K) W1(32K) W3(32K)
constexpr int G1_SMEM  = 2 * G1_STAGE;       // 196608
constexpr int G2_STAGE = 96 * 1024;          // H(64K, 256 rows) W2(32K)
constexpr int G2_SMEM  = 2 * G2_STAGE;       // 196608

// ---------------------------------------------------------------------------
// Scratch (static device globals -- no allocation)
// ---------------------------------------------------------------------------
__device__ __half g_Xh [(size_t)B_ * S_ * D_];   // X fp16,            [B,S,D]
__device__ __half g_W1t[(size_t)B_ * F_ * D_];   // w1[e]^T per batch, [B,F,D]
__device__ __half g_W3t[(size_t)B_ * F_ * D_];   // w3[e]^T per batch, [B,F,D]
__device__ __half g_W2t[(size_t)B_ * D_ * F_];   // w2[e]^T per batch, [B,D,F]
__device__ __half g_H  [(size_t)B_ * S_ * F_];   // gelu(a)*b fp16,    [B,S,F]

// ---------------------------------------------------------------------------
// Helpers (plain PTX, valid at compute_103 -- NO tcgen05 / no 'a'-features)
// ---------------------------------------------------------------------------
DI uint32_t smem_u32(const void* p) {
    uint32_t a;
    asm("{ .reg .u64 t; cvta.to.shared.u64 t, %1; cvt.u32.u64 %0, t; }"
        : "=r"(a) : "l"(p));
    return a;
}

DI uint32_t swz(uint32_t bo) { return bo ^ ((bo >> 3) & 0x70); }   // SW128

DI void ldsm_x4(uint32_t* r, uint32_t addr) {
    asm volatile("ldmatrix.sync.aligned.m8n8.x4.shared.b16 {%0,%1,%2,%3}, [%4];"
                 : "=r"(r[0]), "=r"(r[1]), "=r"(r[2]), "=r"(r[3]) : "r"(addr));
}

DI void mma16816(float* d, const uint32_t* a, const uint32_t* b) {
    asm volatile(
        "mma.sync.aligned.m16n8k16.row.col.f32.f16.f16.f32 "
        "{%0,%1,%2,%3}, {%4,%5,%6,%7}, {%8,%9}, {%0,%1,%2,%3};"
        : "+f"(d[0]), "+f"(d[1]), "+f"(d[2]), "+f"(d[3])
        : "r"(a[0]), "r"(a[1]), "r"(a[2]), "r"(a[3]), "r"(b[0]), "r"(b[1]));
}

DI void cp16(uint32_t dst, const void* src) {
    asm volatile("cp.async.cg.shared.global [%0], [%1], 16;"
                 :: "r"(dst), "l"(src) : "memory");
}
#define CP_COMMIT() asm volatile("cp.async.commit_group;" ::: "memory")
#define CP_WAIT(n)  asm volatile("cp.async.wait_group %0;" :: "n"(n) : "memory")

// Load a [rows x 64] fp16 K-major tile into SW128-swizzled SMEM via cp.async.
template <int NT>
DI void load_tile(const __half* src, int ld, int rows, uint32_t smem_dst, int tid) {
    int nch = rows * 8;                       // 16B chunks
    for (int c = tid; c < nch; c += NT) {
        int row = c >> 3, sub = c & 7;
        uint32_t bo = (uint32_t)(row << 7) | (uint32_t)(sub << 4);
        cp16(smem_dst + swz(bo), src + (size_t)row * ld + sub * 8);
    }
}

DI float gelu_exact(float x) {
    return 0.5f * x * (1.0f + erff(x * 0.70710678118654752f));
}

// ---------------------------------------------------------------------------
// Kernel 1: cast X fp32 -> fp16
// ---------------------------------------------------------------------------
__global__ void cast_x_kernel(const float* __restrict__ x) {
    size_t i = (size_t)blockIdx.x * blockDim.x + threadIdx.x;
    size_t n = (size_t)B_ * S_ * D_ / 4;
    if (i < n) {
        float4 v = reinterpret_cast<const float4*>(x)[i];
        reinterpret_cast<__half2*>(g_Xh)[2 * i]     = __floats2half2_rn(v.x, v.y);
        reinterpret_cast<__half2*>(g_Xh)[2 * i + 1] = __floats2half2_rn(v.z, v.w);
    }
}

// ---------------------------------------------------------------------------
// Kernel 2: gather expert weight, transpose 64x64 tiles, cast, half2 writes.
// WHICH: 0 -> w1 [D,F] -> g_W1t [F,D];  1 -> w3;  2 -> w2 [F,D] -> g_W2t [D,F]
// src [E,R,C]; dst [B,C,R].  Block 32x8.
// ---------------------------------------------------------------------------
template <int WHICH>
__global__ void transpose_cast_kernel(const float* __restrict__ w,
                                      const int* __restrict__ langs,
                                      int R, int C) {
    __shared__ float t[64][65];
    int b = blockIdx.z;
    int e = langs[b] - 4;
    const float* src = w + (size_t)e * R * C;
    __half* dst = ((WHICH == 0) ? g_W1t : (WHICH == 1) ? g_W3t : g_W2t)
                  + (size_t)b * R * C;
    int x0 = blockIdx.x * 64, y0 = blockIdx.y * 64;
    int tx = threadIdx.x, ty = threadIdx.y;
#pragma unroll
    for (int k = 0; k < 8; k++) {
        int r = y0 + ty + 8 * k;
        t[ty + 8 * k][tx]      = src[(size_t)r * C + x0 + tx];
        t[ty + 8 * k][tx + 32] = src[(size_t)r * C + x0 + tx + 32];
    }
    __syncthreads();
#pragma unroll
    for (int k = 0; k < 8; k++) {
        int r = ty + 8 * k;                  // source row within tile (C index)
        __half2 h = __floats2half2_rn(t[2 * tx][r], t[2 * tx + 1][r]);
        *reinterpret_cast<__half2*>(dst + (size_t)(x0 + r) * R + y0 + 2 * tx) = h;
    }
}

// ---------------------------------------------------------------------------
// Kernel 3: GEMM1 + SwiGLU. CTA tile M=128(S) x N=128(F), K=D=1024 in
// 128-chunks. 256 threads, 8 warps as 2(M) x 4(N); warp tile 64x32 with DUAL
// accumulators (one A-frag feeds both W1 and W3 MMAs -> best FLOP/ldsm-byte).
// Double-buffered 96KB stages; ONE __syncthreads per 128-K chunk; fragment
// double-buffering across the 8 ks steps.  Producer cp.async for chunk j+1 is
// DEFERRED to the middle of chunk j's ks loop so its LDGSTS issue burst hides
// under queued MMAs instead of delaying them.  H = gelu(X*W1t)*(X*W3t) (fp16)
// ---------------------------------------------------------------------------
__global__ void __launch_bounds__(256, 1) gemm1_kernel() {
    extern __shared__ char smem[];
    uint32_t sb = smem_u32(smem);
    int tid = threadIdx.x, wid = tid >> 5, lane = tid & 31;
    int s0 = blockIdx.x * 128, f0 = blockIdx.y * 128, b = blockIdx.z;

    const __half* Xp  = g_Xh  + ((size_t)b * S_ + s0) * D_;
    const __half* W1p = g_W1t + ((size_t)b * F_ + f0) * D_;
    const __half* W3p = g_W3t + ((size_t)b * F_ + f0) * D_;

    int wm = wid >> 2, wn = wid & 3;          // warp tile origin: (wm*64, wn*32)
    int li = lane & 7, lj = lane >> 3;
    int arow = wm * 64 + li + (lj & 1) * 8;   // + mi*16
    int akc  = lj >> 1;
    int brow = wn * 32 + li + (lj >> 1) * 8;  // + n2*16
    int bkc  = lj & 1;

    float acc1[4][4][4] = {};
    float acc3[4][4][4] = {};

    // stage sub-layout: X0 X1 W1_0 W1_1 W3_0 W3_1  (6 x 16KB)
    auto load_chunk = [&](int j, uint32_t st) {
        int k0 = j * 128;
        load_tile<256>(Xp  + k0,      D_, 128, st,          tid);
        load_tile<256>(Xp  + k0 + 64, D_, 128, st + 16384,  tid);
        load_tile<256>(W1p + k0,      D_, 128, st + 32768,  tid);
        load_tile<256>(W1p + k0 + 64, D_, 128, st + 49152,  tid);
        load_tile<256>(W3p + k0,      D_, 128, st + 65536,  tid);
        load_tile<256>(W3p + k0 + 64, D_, 128, st + 81920,  tid);
        CP_COMMIT();
    };

    const int NCC = D_ / 128;                 // 8
    load_chunk(0, sb);
    for (int j = 0; j < NCC; ++j) {
        CP_WAIT(0);
        __syncthreads();

        uint32_t stg = sb + (uint32_t)(j & 1) * G1_STAGE;
        uint32_t af[2][4][4], bf1[2][2][4], bf3[2][2][4];
        // frag addresses: half = ks>>2 selects 16KB subtile, ksl = ks&3
        auto a_addr = [&](int ks, int mi) {
            return stg + (uint32_t)(ks >> 2) * 16384u
                 + swz((uint32_t)(arow + mi * 16) * 128
                       + (uint32_t)((ks & 3) * 2 + akc) * 16);
        };
        auto b_addr = [&](int ks, int n2, uint32_t base) {
            return stg + base + (uint32_t)(ks >> 2) * 16384u
                 + swz((uint32_t)(brow + n2 * 16) * 128
                       + (uint32_t)((ks & 3) * 2 + bkc) * 16);
        };
#pragma unroll
        for (int mi = 0; mi < 4; ++mi) ldsm_x4(af[0][mi], a_addr(0, mi));
#pragma unroll
        for (int n2 = 0; n2 < 2; ++n2) {
            ldsm_x4(bf1[0][n2], b_addr(0, n2, 32768u));
            ldsm_x4(bf3[0][n2], b_addr(0, n2, 65536u));
        }
#pragma unroll
        for (int ks = 0; ks < 8; ++ks) {
            const int cur = ks & 1, nxt = cur ^ 1;
            // Deferred producer: issue chunk j+1's cp.async after the first
            // MMA group is queued (ks==1), hiding the LDGSTS burst.
            if (ks == 1 && j + 1 < NCC)
                load_chunk(j + 1, sb + (uint32_t)((j + 1) & 1) * G1_STAGE);
            if (ks < 7) {                     // prefetch next ks frags
#pragma unroll
                for (int mi = 0; mi < 4; ++mi)
                    ldsm_x4(af[nxt][mi], a_addr(ks + 1, mi));
#pragma unroll
                for (int n2 = 0; n2 < 2; ++n2) {
                    ldsm_x4(bf1[nxt][n2], b_addr(ks + 1, n2, 32768u));
                    ldsm_x4(bf3[nxt][n2], b_addr(ks + 1, n2, 65536u));
                }
            }
#pragma unroll
            for (int mi = 0; mi < 4; ++mi)
#pragma unroll
                for (int ni = 0; ni < 4; ++ni) {
                    mma16816(acc1[mi][ni], af[cur][mi], &bf1[cur][ni >> 1][(ni & 1) * 2]);
                    mma16816(acc3[mi][ni], af[cur][mi], &bf3[cur][ni >> 1][(ni & 1) * 2]);
                }
        }
    }

    // Epilogue: gelu(a)*v -> fp16 H
    int r4 = lane >> 2, c2 = (lane & 3) * 2;
#pragma unroll
    for (int mi = 0; mi < 4; ++mi) {
#pragma unroll
        for (int ni = 0; ni < 4; ++ni) {
            int m = s0 + wm * 64 + mi * 16 + r4;
            int n = f0 + wn * 32 + ni * 8 + c2;
            const float* a = acc1[mi][ni];
            const float* v = acc3[mi][ni];
            __half2 h0 = __floats2half2_rn(gelu_exact(a[0]) * v[0],
                                           gelu_exact(a[1]) * v[1]);
            __half2 h1 = __floats2half2_rn(gelu_exact(a[2]) * v[2],
                                           gelu_exact(a[3]) * v[3]);
            *reinterpret_cast<__half2*>(g_H + ((size_t)b * S_ + m) * F_ + n)     = h0;
            *reinterpret_cast<__half2*>(g_H + ((size_t)b * S_ + m + 8) * F_ + n) = h1;
        }
    }
}

// ---------------------------------------------------------------------------
// Kernel 4: GEMM2. CTA tile M=256(S) x N=128(D), K=F=4096 in 128-chunks.
// 512 threads, 16 warps as 4(M) x 4(N); warp tile 64x32, single accumulator,
// single-buffered frags (<=128 regs). Double-buffered 96KB stages; one sync
// per 128-K chunk; deferred producer cp.async (after ks==1's MMA group).
// out = H * W2t (fp32; routing weight == 1: langs in [4,12))
// ---------------------------------------------------------------------------
__global__ void __launch_bounds__(512, 1) gemm2_kernel(float* __restrict__ out) {
    extern __shared__ char smem[];
    uint32_t sb = smem_u32(smem);
    int tid = threadIdx.x, wid = tid >> 5, lane = tid & 31;
    int s0 = blockIdx.x * 256, d0 = blockIdx.y * 128, b = blockIdx.z;

    const __half* Hp  = g_H   + ((size_t)b * S_ + s0) * F_;
    const __half* W2p = g_W2t + ((size_t)b * D_ + d0) * F_;

    int wm = wid >> 2, wn = wid & 3;          // warp tile origin: (wm*64, wn*32)
    int li = lane & 7, lj = lane >> 3;
    int arow = wm * 64 + li + (lj & 1) * 8;   // + mi*16
    int akc  = lj >> 1;
    int brow = wn * 32 + li + (lj >> 1) * 8;  // + n2*16
    int bkc  = lj & 1;

    float acc[4][4][4] = {};                  // 64 regs

    // stage sub-layout: H0(32K) H1(32K) W2_0(16K) W2_1(16K)
    auto load_chunk = [&](int j, uint32_t st) {
        int k0 = j * 128;
        load_tile<512>(Hp  + k0,      F_, 256, st,          tid);
        load_tile<512>(Hp  + k0 + 64, F_, 256, st + 32768,  tid);
        load_tile<512>(W2p + k0,      F_, 128, st + 65536,  tid);
        load_tile<512>(W2p + k0 + 64, F_, 128, st + 81920,  tid);
        CP_COMMIT();
    };

    const int NCC = F_ / 128;                 // 32
    load_chunk(0, sb);
    for (int j = 0; j < NCC; ++j) {
        CP_WAIT(0);
        __syncthreads();

        uint32_t stg = sb + (uint32_t)(j & 1) * G2_STAGE;
#pragma unroll
        for (int ks = 0; ks < 8; ++ks) {
            if (ks == 1 && j + 1 < NCC)
                load_chunk(j + 1, sb + (uint32_t)((j + 1) & 1) * G2_STAGE);
            uint32_t ah = stg + (uint32_t)(ks >> 2) * 32768u;
            uint32_t bh = stg + 65536u + (uint32_t)(ks >> 2) * 16384u;
            uint32_t af[4][4], bf[2][4];
#pragma unroll
            for (int mi = 0; mi < 4; ++mi)
                ldsm_x4(af[mi], ah + swz((uint32_t)(arow + mi * 16) * 128
                                         + (uint32_t)((ks & 3) * 2 + akc) * 16));
#pragma unroll
            for (int n2 = 0; n2 < 2; ++n2)
                ldsm_x4(bf[n2], bh + swz((uint32_t)(brow + n2 * 16) * 128
                                         + (uint32_t)((ks & 3) * 2 + bkc) * 16));
#pragma unroll
            for (int mi = 0; mi < 4; ++mi)
#pragma unroll
                for (int ni = 0; ni < 4; ++ni)
                    mma16816(acc[mi][ni], af[mi], &bf[ni >> 1][(ni & 1) * 2]);
        }
    }

    int r4 = lane >> 2, c2 = (lane & 3) * 2;
#pragma unroll
    for (int mi = 0; mi < 4; ++mi) {
#pragma unroll
        for (int ni = 0; ni < 4; ++ni) {
            int m = s0 + wm * 64 + mi * 16 + r4;
            int n = d0 + wn * 32 + ni * 8 + c2;
            const float* c = acc[mi][ni];
            *reinterpret_cast<float2*>(out + ((size_t)b * S_ + m) * D_ + n) =
                make_float2(c[0], c[1]);
            *reinterpret_cast<float2*>(out + ((size_t)b * S_ + m + 8) * D_ + n) =
                make_float2(c[2], c[3]);
        }
    }
}

// ---------------------------------------------------------------------------
// Launch.  Order keeps gemm1 in ncu's capture slot (4th kernel launch).
// ---------------------------------------------------------------------------
extern "C" void kernel_launch(void* const* d_in, const int* in_sizes, int n_in,
                              void* d_out, int out_size) {
    (void)in_sizes; (void)n_in; (void)out_size;
    const float* hs    = (const float*)d_in[0];
    const float* w1    = (const float*)d_in[1];
    const float* w2    = (const float*)d_in[2];
    const float* w3    = (const float*)d_in[3];
    const int*   langs = (const int*)d_in[4];
    float* out = (float*)d_out;

    cudaFuncSetAttribute(gemm1_kernel, cudaFuncAttributeMaxDynamicSharedMemorySize, G1_SMEM);
    cudaFuncSetAttribute(gemm2_kernel, cudaFuncAttributeMaxDynamicSharedMemorySize, G2_SMEM);

    cast_x_kernel<<<(B_ * S_ * D_ / 4 + 255) / 256, 256>>>(hs);

    dim3 tb(32, 8);
    transpose_cast_kernel<0><<<dim3(F_ / 64, D_ / 64, B_), tb>>>(w1, langs, D_, F_);
    transpose_cast_kernel<1><<<dim3(F_ / 64, D_ / 64, B_), tb>>>(w3, langs, D_, F_);

    gemm1_kernel<<<dim3(S_ / 128, F_ / 128, B_), 256, G1_SMEM>>>();

    transpose_cast_kernel<2><<<dim3(D_ / 64, F_ / 64, B_), tb>>>(w2, langs, F_, D_);

    gemm2_kernel<<<dim3(S_ / 256, D_ / 128, B_), 512, G2_SMEM>>>(out);
}

// round 16
// speedup vs baseline: 1.0089x; 1.0089x over previous
#include <cuda_runtime.h>
#include <cuda_fp16.h>
#include <cstdint>
#include <cstddef>

#define DI __device__ __forceinline__

// ---------------------------------------------------------------------------
// Problem constants
// ---------------------------------------------------------------------------
constexpr int B_ = 8;
constexpr int S_ = 2048;
constexpr int D_ = 1024;
constexpr int F_ = 4096;

// K per pipeline chunk = 128 (two 64-col subtiles per operand per stage).
// Double-buffered stages -> single __syncthreads per 128-K chunk.
constexpr int G1_STAGE = 96 * 1024;          // X(32K) W1(32K) W3(32K)
constexpr int G1_SMEM  = 2 * G1_STAGE;       // 196608
constexpr int G2_STAGE = 96 * 1024;          // H(64K, 256 rows) W2(32K)
constexpr int G2_SMEM  = 2 * G2_STAGE;       // 196608

// ---------------------------------------------------------------------------
// Scratch (static device globals -- no allocation)
// ---------------------------------------------------------------------------
__device__ __half g_Xh [(size_t)B_ * S_ * D_];   // X fp16,            [B,S,D]
__device__ __half g_W1t[(size_t)B_ * F_ * D_];   // w1[e]^T per batch, [B,F,D]
__device__ __half g_W3t[(size_t)B_ * F_ * D_];   // w3[e]^T per batch, [B,F,D]
__device__ __half g_W2t[(size_t)B_ * D_ * F_];   // w2[e]^T per batch, [B,D,F]
__device__ __half g_H  [(size_t)B_ * S_ * F_];   // gelu(a)*b fp16,    [B,S,F]

// ---------------------------------------------------------------------------
// Helpers (plain PTX, valid at compute_103 -- NO tcgen05 / no 'a'-features)
// ---------------------------------------------------------------------------
DI uint32_t smem_u32(const void* p) {
    uint32_t a;
    asm("{ .reg .u64 t; cvta.to.shared.u64 t, %1; cvt.u32.u64 %0, t; }"
        : "=r"(a) : "l"(p));
    return a;
}

DI uint32_t swz(uint32_t bo) { return bo ^ ((bo >> 3) & 0x70); }   // SW128

DI void ldsm_x4(uint32_t* r, uint32_t addr) {
    asm volatile("ldmatrix.sync.aligned.m8n8.x4.shared.b16 {%0,%1,%2,%3}, [%4];"
                 : "=r"(r[0]), "=r"(r[1]), "=r"(r[2]), "=r"(r[3]) : "r"(addr));
}

DI void mma16816(float* d, const uint32_t* a, const uint32_t* b) {
    asm volatile(
        "mma.sync.aligned.m16n8k16.row.col.f32.f16.f16.f32 "
        "{%0,%1,%2,%3}, {%4,%5,%6,%7}, {%8,%9}, {%0,%1,%2,%3};"
        : "+f"(d[0]), "+f"(d[1]), "+f"(d[2]), "+f"(d[3])
        : "r"(a[0]), "r"(a[1]), "r"(a[2]), "r"(a[3]), "r"(b[0]), "r"(b[1]));
}

DI void cp16(uint32_t dst, const void* src) {
    asm volatile("cp.async.cg.shared.global [%0], [%1], 16;"
                 :: "r"(dst), "l"(src) : "memory");
}
#define CP_COMMIT() asm volatile("cp.async.commit_group;" ::: "memory")
#define CP_WAIT(n)  asm volatile("cp.async.wait_group %0;" :: "n"(n) : "memory")

// Load a [rows x 64] fp16 K-major tile into SW128-swizzled SMEM via cp.async.
template <int NT>
DI void load_tile(const __half* src, int ld, int rows, uint32_t smem_dst, int tid) {
    int nch = rows * 8;                       // 16B chunks
    for (int c = tid; c < nch; c += NT) {
        int row = c >> 3, sub = c & 7;
        uint32_t bo = (uint32_t)(row << 7) | (uint32_t)(sub << 4);
        cp16(smem_dst + swz(bo), src + (size_t)row * ld + sub * 8);
    }
}

DI float gelu_exact(float x) {
    return 0.5f * x * (1.0f + erff(x * 0.70710678118654752f));
}

// ---------------------------------------------------------------------------
// Kernel 1: cast X fp32 -> fp16
// ---------------------------------------------------------------------------
__global__ void cast_x_kernel(const float* __restrict__ x) {
    size_t i = (size_t)blockIdx.x * blockDim.x + threadIdx.x;
    size_t n = (size_t)B_ * S_ * D_ / 4;
    if (i < n) {
        float4 v = reinterpret_cast<const float4*>(x)[i];
        reinterpret_cast<__half2*>(g_Xh)[2 * i]     = __floats2half2_rn(v.x, v.y);
        reinterpret_cast<__half2*>(g_Xh)[2 * i + 1] = __floats2half2_rn(v.z, v.w);
    }
}

// ---------------------------------------------------------------------------
// Kernel 2: gather expert weight, transpose 64x64 tiles, cast, half2 writes.
// WHICH: 0 -> w1 [D,F] -> g_W1t [F,D];  1 -> w3;  2 -> w2 [F,D] -> g_W2t [D,F]
// src [E,R,C]; dst [B,C,R].  Block 32x8.
// ---------------------------------------------------------------------------
template <int WHICH>
__global__ void transpose_cast_kernel(const float* __restrict__ w,
                                      const int* __restrict__ langs,
                                      int R, int C) {
    __shared__ float t[64][65];
    int b = blockIdx.z;
    int e = langs[b] - 4;
    const float* src = w + (size_t)e * R * C;
    __half* dst = ((WHICH == 0) ? g_W1t : (WHICH == 1) ? g_W3t : g_W2t)
                  + (size_t)b * R * C;
    int x0 = blockIdx.x * 64, y0 = blockIdx.y * 64;
    int tx = threadIdx.x, ty = threadIdx.y;
#pragma unroll
    for (int k = 0; k < 8; k++) {
        int r = y0 + ty + 8 * k;
        t[ty + 8 * k][tx]      = src[(size_t)r * C + x0 + tx];
        t[ty + 8 * k][tx + 32] = src[(size_t)r * C + x0 + tx + 32];
    }
    __syncthreads();
#pragma unroll
    for (int k = 0; k < 8; k++) {
        int r = ty + 8 * k;                  // source row within tile (C index)
        __half2 h = __floats2half2_rn(t[2 * tx][r], t[2 * tx + 1][r]);
        *reinterpret_cast<__half2*>(dst + (size_t)(x0 + r) * R + y0 + 2 * tx) = h;
    }
}

// ---------------------------------------------------------------------------
// Kernel 3: GEMM1 + SwiGLU. CTA tile M=128(S) x N=128(F), K=D=1024 in
// 128-chunks. 512 threads / 16 warps as 2(M) x 8(N); warp tile 64x16 with
// DUAL accumulators. Same MMA:ldsm ratio (2.67) and same total ldsm traffic
// as the 8-warp 64x32 shape, but ~110 regs -> 4 warps/SMSP: TLP covers ldsm
// latency (single-buffered frags). One __syncthreads per 128-K chunk;
// deferred producer cp.async.  H = gelu(X*W1t)*(X*W3t) (fp16)
// ---------------------------------------------------------------------------
__global__ void __launch_bounds__(512, 1) gemm1_kernel() {
    extern __shared__ char smem[];
    uint32_t sb = smem_u32(smem);
    int tid = threadIdx.x, wid = tid >> 5, lane = tid & 31;
    int s0 = blockIdx.x * 128, f0 = blockIdx.y * 128, b = blockIdx.z;

    const __half* Xp  = g_Xh  + ((size_t)b * S_ + s0) * D_;
    const __half* W1p = g_W1t + ((size_t)b * F_ + f0) * D_;
    const __half* W3p = g_W3t + ((size_t)b * F_ + f0) * D_;

    int wm = wid >> 3, wn = wid & 7;          // warp tile origin: (wm*64, wn*16)
    int li = lane & 7, lj = lane >> 3;
    int arow = wm * 64 + li + (lj & 1) * 8;   // + mi*16
    int akc  = lj >> 1;
    int brow = wn * 16 + li + (lj >> 1) * 8;
    int bkc  = lj & 1;

    float acc1[4][2][4] = {};                 // 32 regs
    float acc3[4][2][4] = {};                 // 32 regs

    // stage sub-layout: X0 X1 W1_0 W1_1 W3_0 W3_1  (6 x 16KB)
    auto load_chunk = [&](int j, uint32_t st) {
        int k0 = j * 128;
        load_tile<512>(Xp  + k0,      D_, 128, st,          tid);
        load_tile<512>(Xp  + k0 + 64, D_, 128, st + 16384,  tid);
        load_tile<512>(W1p + k0,      D_, 128, st + 32768,  tid);
        load_tile<512>(W1p + k0 + 64, D_, 128, st + 49152,  tid);
        load_tile<512>(W3p + k0,      D_, 128, st + 65536,  tid);
        load_tile<512>(W3p + k0 + 64, D_, 128, st + 81920,  tid);
        CP_COMMIT();
    };

    const int NCC = D_ / 128;                 // 8
    load_chunk(0, sb);
    for (int j = 0; j < NCC; ++j) {
        CP_WAIT(0);
        __syncthreads();

        uint32_t stg = sb + (uint32_t)(j & 1) * G1_STAGE;
#pragma unroll
        for (int ks = 0; ks < 8; ++ks) {
            // Deferred producer: issue chunk j+1's cp.async after the first
            // MMA group is queued (ks==1), hiding the LDGSTS burst.
            if (ks == 1 && j + 1 < NCC)
                load_chunk(j + 1, sb + (uint32_t)((j + 1) & 1) * G1_STAGE);

            uint32_t half = (uint32_t)(ks >> 2) * 16384u;
            uint32_t koff = (uint32_t)((ks & 3) * 2) * 16u;
            uint32_t af[4][4], bf1[4], bf3[4];
#pragma unroll
            for (int mi = 0; mi < 4; ++mi)
                ldsm_x4(af[mi], stg + half
                        + swz((uint32_t)(arow + mi * 16) * 128
                              + koff + (uint32_t)akc * 16));
            {
                uint32_t bo = swz((uint32_t)brow * 128 + koff + (uint32_t)bkc * 16);
                ldsm_x4(bf1, stg + 32768u + half + bo);
                ldsm_x4(bf3, stg + 65536u + half + bo);
            }
#pragma unroll
            for (int mi = 0; mi < 4; ++mi)
#pragma unroll
                for (int ni = 0; ni < 2; ++ni) {
                    mma16816(acc1[mi][ni], af[mi], &bf1[ni * 2]);
                    mma16816(acc3[mi][ni], af[mi], &bf3[ni * 2]);
                }
        }
    }

    // Epilogue: gelu(a)*v -> fp16 H
    int r4 = lane >> 2, c2 = (lane & 3) * 2;
#pragma unroll
    for (int mi = 0; mi < 4; ++mi) {
#pragma unroll
        for (int ni = 0; ni < 2; ++ni) {
            int m = s0 + wm * 64 + mi * 16 + r4;
            int n = f0 + wn * 16 + ni * 8 + c2;
            const float* a = acc1[mi][ni];
            const float* v = acc3[mi][ni];
            __half2 h0 = __floats2half2_rn(gelu_exact(a[0]) * v[0],
                                           gelu_exact(a[1]) * v[1]);
            __half2 h1 = __floats2half2_rn(gelu_exact(a[2]) * v[2],
                                           gelu_exact(a[3]) * v[3]);
            *reinterpret_cast<__half2*>(g_H + ((size_t)b * S_ + m) * F_ + n)     = h0;
            *reinterpret_cast<__half2*>(g_H + ((size_t)b * S_ + m + 8) * F_ + n) = h1;
        }
    }
}

// ---------------------------------------------------------------------------
// Kernel 4: GEMM2. CTA tile M=256(S) x N=128(D), K=F=4096 in 128-chunks.
// 512 threads, 16 warps as 4(M) x 4(N); warp tile 64x32, single accumulator,
// single-buffered frags (<=128 regs). Double-buffered 96KB stages; one sync
// per 128-K chunk; deferred producer cp.async (after ks==1's MMA group).
// out = H * W2t (fp32; routing weight == 1: langs in [4,12))
// ---------------------------------------------------------------------------
__global__ void __launch_bounds__(512, 1) gemm2_kernel(float* __restrict__ out) {
    extern __shared__ char smem[];
    uint32_t sb = smem_u32(smem);
    int tid = threadIdx.x, wid = tid >> 5, lane = tid & 31;
    int s0 = blockIdx.x * 256, d0 = blockIdx.y * 128, b = blockIdx.z;

    const __half* Hp  = g_H   + ((size_t)b * S_ + s0) * F_;
    const __half* W2p = g_W2t + ((size_t)b * D_ + d0) * F_;

    int wm = wid >> 2, wn = wid & 3;          // warp tile origin: (wm*64, wn*32)
    int li = lane & 7, lj = lane >> 3;
    int arow = wm * 64 + li + (lj & 1) * 8;   // + mi*16
    int akc  = lj >> 1;
    int brow = wn * 32 + li + (lj >> 1) * 8;  // + n2*16
    int bkc  = lj & 1;

    float acc[4][4][4] = {};                  // 64 regs

    // stage sub-layout: H0(32K) H1(32K) W2_0(16K) W2_1(16K)
    auto load_chunk = [&](int j, uint32_t st) {
        int k0 = j * 128;
        load_tile<512>(Hp  + k0,      F_, 256, st,          tid);
        load_tile<512>(Hp  + k0 + 64, F_, 256, st + 32768,  tid);
        load_tile<512>(W2p + k0,      F_, 128, st + 65536,  tid);
        load_tile<512>(W2p + k0 + 64, F_, 128, st + 81920,  tid);
        CP_COMMIT();
    };

    const int NCC = F_ / 128;                 // 32
    load_chunk(0, sb);
    for (int j = 0; j < NCC; ++j) {
        CP_WAIT(0);
        __syncthreads();

        uint32_t stg = sb + (uint32_t)(j & 1) * G2_STAGE;
#pragma unroll
        for (int ks = 0; ks < 8; ++ks) {
            if (ks == 1 && j + 1 < NCC)
                load_chunk(j + 1, sb + (uint32_t)((j + 1) & 1) * G2_STAGE);
            uint32_t ah = stg + (uint32_t)(ks >> 2) * 32768u;
            uint32_t bh = stg + 65536u + (uint32_t)(ks >> 2) * 16384u;
            uint32_t af[4][4], bf[2][4];
#pragma unroll
            for (int mi = 0; mi < 4; ++mi)
                ldsm_x4(af[mi], ah + swz((uint32_t)(arow + mi * 16) * 128
                                         + (uint32_t)((ks & 3) * 2 + akc) * 16));
#pragma unroll
            for (int n2 = 0; n2 < 2; ++n2)
                ldsm_x4(bf[n2], bh + swz((uint32_t)(brow + n2 * 16) * 128
                                         + (uint32_t)((ks & 3) * 2 + bkc) * 16));
#pragma unroll
            for (int mi = 0; mi < 4; ++mi)
#pragma unroll
                for (int ni = 0; ni < 4; ++ni)
                    mma16816(acc[mi][ni], af[mi], &bf[ni >> 1][(ni & 1) * 2]);
        }
    }

    int r4 = lane >> 2, c2 = (lane & 3) * 2;
#pragma unroll
    for (int mi = 0; mi < 4; ++mi) {
#pragma unroll
        for (int ni = 0; ni < 4; ++ni) {
            int m = s0 + wm * 64 + mi * 16 + r4;
            int n = d0 + wn * 32 + ni * 8 + c2;
            const float* c = acc[mi][ni];
            *reinterpret_cast<float2*>(out + ((size_t)b * S_ + m) * D_ + n) =
                make_float2(c[0], c[1]);
            *reinterpret_cast<float2*>(out + ((size_t)b * S_ + m + 8) * D_ + n) =
                make_float2(c[2], c[3]);
        }
    }
}

// ---------------------------------------------------------------------------
// Launch.  Order keeps gemm1 in ncu's capture slot (4th kernel launch).
// ---------------------------------------------------------------------------
extern "C" void kernel_launch(void* const* d_in, const int* in_sizes, int n_in,
                              void* d_out, int out_size) {
    (void)in_sizes; (void)n_in; (void)out_size;
    const float* hs    = (const float*)d_in[0];
    const float* w1    = (const float*)d_in[1];
    const float* w2    = (const float*)d_in[2];
    const float* w3    = (const float*)d_in[3];
    const int*   langs = (const int*)d_in[4];
    float* out = (float*)d_out;

    cudaFuncSetAttribute(gemm1_kernel, cudaFuncAttributeMaxDynamicSharedMemorySize, G1_SMEM);
    cudaFuncSetAttribute(gemm2_kernel, cudaFuncAttributeMaxDynamicSharedMemorySize, G2_SMEM);

    cast_x_kernel<<<(B_ * S_ * D_ / 4 + 255) / 256, 256>>>(hs);

    dim3 tb(32, 8);
    transpose_cast_kernel<0><<<dim3(F_ / 64, D_ / 64, B_), tb>>>(w1, langs, D_, F_);
    transpose_cast_kernel<1><<<dim3(F_ / 64, D_ / 64, B_), tb>>>(w3, langs, D_, F_);

    gemm1_kernel<<<dim3(S_ / 128, F_ / 128, B_), 512, G1_SMEM>>>();

    transpose_cast_kernel<2><<<dim3(D_ / 64, F_ / 64, B_), tb>>>(w2, langs, F_, D_);

    gemm2_kernel<<<dim3(S_ / 256, D_ / 128, B_), 512, G2_SMEM>>>(out);
}